// round 13
// baseline (speedup 1.0000x reference)
#include <cuda_runtime.h>
#include <cuda_bf16.h>
#include <math.h>

// ---------------------------------------------------------------------------
// AsymmetricLossCustomPriorityRankNewNegOne  (B=4096, C=9605, L=20)
// TWO warps per row, each owning a 512-col half. One fused y+x epoch,
// shared-memory combine (2 bars), wl rows finish from registers, other rows
// take one extra half-size yneg epoch. Fast path device-verified.
// ---------------------------------------------------------------------------

#define MAXC 16384
#define JINF 0x7fffffff

__device__ unsigned            g_bits[MAXC];
__device__ unsigned long long  g_pack[MAXC];   // (bits<<32 | c)  [slow path]
__device__ int                 g_ucount;
__device__ int                 g_cmin;
__device__ int                 g_cmax;
__device__ int                 g_notfast;
__device__ int                 g_gs;           // uniform group size candidate
__device__ int                 g_is_u8;

__device__ __forceinline__ unsigned enc_f(float f) {
    unsigned u = __float_as_uint(f);
    return (u & 0x80000000u) ? ~u : (u | 0x80000000u);
}
__device__ __forceinline__ float dec_f(unsigned u) {
    return __uint_as_float((u & 0x80000000u) ? (u & 0x7fffffffu) : ~u);
}
__device__ __forceinline__ float sigmoidf_(float x) {
    return 1.0f / (1.0f + expf(-x));
}
// d = x2 - x1 + 0.05; s = sigmoid(10 d); d>0 -> 2s else s
__device__ __forceinline__ float rank_loss_(float x1, float x2) {
    float d = x2 - x1 + 0.05f;
    float s = sigmoidf_(10.0f * d);
    return (d > 0.0f) ? 2.0f * s : s;
}

// --- kernel 1: init + parallel width detect ----------------------------------
__global__ void init_kernel(float* out, int out_size,
                            const unsigned int* wl_as_u32, int n_probe) {
    __shared__ int flag;
    int t = threadIdx.x;
    if (t == 0) flag = 0;
    __syncthreads();
    for (int i = t; i < out_size; i += blockDim.x) out[i] = 0.0f;
    if (t < n_probe && wl_as_u32[t] > 1u) flag = 1;
    __syncthreads();
    if (t == 0) {
        g_is_u8   = flag;
        g_ucount  = 0;
        g_cmin    = 0x7fffffff;
        g_cmax    = -1;
        g_notfast = 0;
        g_gs      = 0;
    }
}

// --- kernel 2: per-class group bitmask + stats ---------------------------------
__global__ void build_bits_kernel(const void* wl, int C, int L) {
    __shared__ int bmin, bmax, bbad, bgs;
    if (threadIdx.x == 0) { bmin = 0x7fffffff; bmax = -1; bbad = 0; bgs = 0; }
    __syncthreads();

    int c = blockIdx.x * blockDim.x + threadIdx.x;
    unsigned b = 0;
    if (c < C) {
        if (g_is_u8) {
            const unsigned char* m = (const unsigned char*)wl;
            #pragma unroll 4
            for (int l = 0; l < L; l++)
                if (m[(size_t)l * C + c]) b |= (1u << l);
        } else {
            const int* m = (const int*)wl;
            #pragma unroll 4
            for (int l = 0; l < L; l++)
                if (m[(size_t)l * C + c]) b |= (1u << l);
        }
        g_bits[c] = b;
        if (b) {
            atomicMin(&bmin, c);
            atomicMax(&bmax, c);
            if (__popc(b) > 1) bbad = 1;
            if (b == 1u) atomicAdd(&bgs, 1);
        }
    }
    __syncthreads();
    if (threadIdx.x == 0) {
        if (bmax >= 0) { atomicMin(&g_cmin, bmin); atomicMax(&g_cmax, bmax); }
        if (bbad) g_notfast = 1;
        if (bgs)  atomicAdd(&g_gs, bgs);
    }
}

// --- kernel 3: compaction + exact fast-path verification -----------------------
__global__ void compact_kernel(int C) {
    __shared__ int woff[8];
    __shared__ int sbase;
    int c    = blockIdx.x * 256 + threadIdx.x;
    int lane = threadIdx.x & 31;
    int wid  = threadIdx.x >> 5;

    unsigned b = (c < C) ? g_bits[c] : 0u;
    unsigned ballot = __ballot_sync(0xffffffffu, b != 0u);
    if (lane == 0) woff[wid] = __popc(ballot);
    __syncthreads();
    if (threadIdx.x == 0) {
        int acc = 0;
        #pragma unroll
        for (int w = 0; w < 8; w++) { int t = woff[w]; woff[w] = acc; acc += t; }
        sbase = atomicAdd(&g_ucount, acc);
    }
    __syncthreads();
    if (b) {
        int pos = sbase + woff[wid] + __popc(ballot & ((1u << lane) - 1u));
        g_pack[pos] = ((unsigned long long)b << 32) | (unsigned)c;

        int gs = g_gs;
        if (gs > 0) {
            unsigned M = (4194304u + (unsigned)gs - 1u) / (unsigned)gs;
            unsigned j = (unsigned)(c - g_cmin);
            unsigned gm = (j * M) >> 22;
            if ((int)gm != (__ffs(b) - 1) || gm >= 32u) g_notfast = 1;
        } else {
            g_notfast = 1;
        }
    }
}

// --- kernel 4: 2-warps-per-row fused loss ----------------------------------------
__global__ __launch_bounds__(128, 7)
void row_loss_kernel(const float* __restrict__ x,
                     const int*   __restrict__ y,
                     const int*   __restrict__ yneg,
                     int C, int B, float* __restrict__ out) {
    const int lane = threadIdx.x & 31;
    const int wid  = threadIdx.x >> 5;
    const int rib  = wid >> 1;             // row-in-block: 0 or 1
    const int half = wid & 1;              // which half of the row
    const int row  = blockIdx.x + rib * gridDim.x;   // mixes wl/other per block

    const int n    = g_ucount;
    const int cmin = g_cmin;
    const bool fast = (!g_notfast) && (g_cmax - cmin + 1 == n);

    if (fast) {
        __shared__ float sSum;
        __shared__ int sJ[2];
        __shared__ unsigned sMN[2], sMW[2], sGM[2];
        const unsigned KNEG = enc_f(-1e30f);
        if (threadIdx.x < 2) {
            sJ[threadIdx.x]  = JINF;
            sMN[threadIdx.x] = KNEG;
            sMW[threadIdx.x] = KNEG;
            sGM[threadIdx.x] = KNEG;
        }
        if (threadIdx.x == 0) sSum = 0.0f;
        __syncthreads();                                   // bar 0

        const int gs = g_gs;
        const unsigned M = (4194304u + (unsigned)gs - 1u) / (unsigned)gs;
        const long long base = (long long)row * C + cmin;
        const float* __restrict__ xr  = x    + base;
        const int*   __restrict__ yr  = y    + base;
        const int*   __restrict__ ynr = yneg + base;

        int p = (int)((4 - (base & 3)) & 3);
        if (p > n) p = n;
        const int nv = (n - p) >> 2;                       // vec4 chunks
        const int ts = p + 4 * nv;
        const int ntail = n - ts;
        const int c0 = half * 128;                         // this warp's chunk base
        const int cover_end = p + 4 * min(nv, 256);        // register-covered cols

        // ============== epoch 1: y + x over this half (8 loads) =============
        int4   yv[4];
        float4 xv[4];
        const int   ypeel = (half == 0 && lane < p)     ? __ldg(yr + lane)      : 0;
        const float xpeel = (half == 0 && lane < p)     ? __ldg(xr + lane)      : -1e30f;
        const int   ytail = (half == 1 && lane < ntail) ? __ldg(yr + ts + lane) : 0;
        const float xtail = (half == 1 && lane < ntail) ? __ldg(xr + ts + lane) : -1e30f;
        #pragma unroll
        for (int k = 0; k < 4; k++) {
            const int i = c0 + lane + k * 32;
            if (i < nv) {
                yv[k] = __ldg((const int4*)  (yr + p + 4 * i));
                xv[k] = __ldg((const float4*)(xr + p + 4 * i));
            } else {
                yv[k] = make_int4(0, 0, 0, 0);
                xv[k] = make_float4(-1e30f, -1e30f, -1e30f, -1e30f);
            }
        }

        // first positive column (local) + mN (local)
        int jmin = JINF;
        float mN = fmaxf(xpeel, xtail);
        #pragma unroll
        for (int k = 0; k < 4; k++) {
            mN = fmaxf(mN, fmaxf(fmaxf(xv[k].x, xv[k].y), fmaxf(xv[k].z, xv[k].w)));
            if ((yv[k].x | yv[k].y | yv[k].z | yv[k].w) && jmin == JINF) {
                const int j0 = p + 4 * (c0 + lane + k * 32);
                if      (yv[k].x) jmin = j0;
                else if (yv[k].y) jmin = j0 + 1;
                else if (yv[k].z) jmin = j0 + 2;
                else              jmin = j0 + 3;
            }
        }
        // rare overflow cols (n > 1027): half 1 scans them scalar
        if (half == 1) {
            for (int i = 256 + lane; i < nv; i += 32) {
                const int4   yo = __ldg((const int4*)  (yr + p + 4 * i));
                const float4 xo = __ldg((const float4*)(xr + p + 4 * i));
                mN = fmaxf(mN, fmaxf(fmaxf(xo.x, xo.y), fmaxf(xo.z, xo.w)));
                if ((yo.x | yo.y | yo.z | yo.w) && jmin == JINF) {
                    const int j0 = p + 4 * i;
                    if      (yo.x) jmin = j0;
                    else if (yo.y) jmin = j0 + 1;
                    else if (yo.z) jmin = j0 + 2;
                    else           jmin = j0 + 3;
                }
            }
        }
        if (ypeel && lane < jmin) jmin = lane;
        if (ytail && jmin == JINF) jmin = ts + lane;
        #pragma unroll
        for (int off = 16; off > 0; off >>= 1)
            jmin = min(jmin, __shfl_xor_sync(0xffffffffu, jmin, off));
        if (lane == 0 && jmin != JINF) atomicMin(&sJ[rib], jmin);
        __syncthreads();                                   // bar 1

        const int jrow = sJ[rib];
        if (jrow != JINF) {
            // ---- wl row: priority-group max from register-held x ----
            const int fl = (int)(((unsigned)jrow * M) >> 22);
            const int lo = fl * gs;
            const int hi = min(lo + gs, n);
            float m = -1e30f;
            if (half == 0 && lane < p && lane >= lo && lane < hi)
                m = fmaxf(m, xpeel);
            #pragma unroll
            for (int k = 0; k < 4; k++) {
                const int j0 = p + 4 * (c0 + lane + k * 32);
                if (j0 + 3 >= lo && j0 < hi) {
                    if (j0     >= lo && j0     < hi) m = fmaxf(m, xv[k].x);
                    if (j0 + 1 >= lo && j0 + 1 < hi) m = fmaxf(m, xv[k].y);
                    if (j0 + 2 >= lo && j0 + 2 < hi) m = fmaxf(m, xv[k].z);
                    if (j0 + 3 >= lo && j0 + 3 < hi) m = fmaxf(m, xv[k].w);
                }
            }
            if (half == 1) {
                const int j = ts + lane;
                if (lane < ntail && j >= lo && j < hi) m = fmaxf(m, xtail);
                // rare: group extends past register coverage
                for (int j2 = lo + lane; j2 < hi; j2 += 32)
                    if (j2 >= cover_end && j2 < ts) m = fmaxf(m, __ldg(xr + j2));
            }
            #pragma unroll
            for (int off = 16; off > 0; off >>= 1)
                m = fmaxf(m, __shfl_xor_sync(0xffffffffu, m, off));
            if (lane == 0) atomicMax(&sGM[rib], enc_f(m));
        } else {
            // ---- other row: epoch 2 = yneg over this half (4 loads) ----
            int4 nvv[4];
            const int npeel = (half == 0 && lane < p)     ? __ldg(ynr + lane)      : 0;
            const int ntl   = (half == 1 && lane < ntail) ? __ldg(ynr + ts + lane) : 0;
            #pragma unroll
            for (int k = 0; k < 4; k++) {
                const int i = c0 + lane + k * 32;
                nvv[k] = (i < nv) ? __ldg((const int4*)(ynr + p + 4 * i))
                                  : make_int4(0, 0, 0, 0);
            }
            float mW = -1e30f;
            if (npeel) mW = fmaxf(mW, xpeel);
            if (ntl)   mW = fmaxf(mW, xtail);
            #pragma unroll
            for (int k = 0; k < 4; k++) {
                mW = fmaxf(mW, nvv[k].x ? xv[k].x : -1e30f);
                mW = fmaxf(mW, nvv[k].y ? xv[k].y : -1e30f);
                mW = fmaxf(mW, nvv[k].z ? xv[k].z : -1e30f);
                mW = fmaxf(mW, nvv[k].w ? xv[k].w : -1e30f);
            }
            if (half == 1) {
                for (int i = 256 + lane; i < nv; i += 32) {    // rare overflow
                    const float4 xo = __ldg((const float4*)(xr  + p + 4 * i));
                    const int4   no = __ldg((const int4*)  (ynr + p + 4 * i));
                    mW = fmaxf(mW, no.x ? xo.x : -1e30f);
                    mW = fmaxf(mW, no.y ? xo.y : -1e30f);
                    mW = fmaxf(mW, no.z ? xo.z : -1e30f);
                    mW = fmaxf(mW, no.w ? xo.w : -1e30f);
                }
            }
            #pragma unroll
            for (int off = 16; off > 0; off >>= 1) {
                mN = fmaxf(mN, __shfl_xor_sync(0xffffffffu, mN, off));
                mW = fmaxf(mW, __shfl_xor_sync(0xffffffffu, mW, off));
            }
            if (lane == 0) {
                atomicMax(&sMN[rib], enc_f(mN));
                atomicMax(&sMW[rib], enc_f(mW));
            }
        }
        __syncthreads();                                   // bar 2

        if (lane == 0 && half == 0 && row < B) {
            float loss;
            if (sJ[rib] != JINF) {
                loss = rank_loss_(sigmoidf_(dec_f(sGM[rib])), 0.5f);
            } else {
                loss = 0.5f * rank_loss_(0.5f, sigmoidf_(dec_f(sMN[rib])))
                     + 0.5f * rank_loss_(0.5f, sigmoidf_(dec_f(sMW[rib])));
            }
            atomicAdd(&sSum, loss);
        }
        __syncthreads();                                   // bar 3
        if (threadIdx.x == 0) atomicAdd(out, sSum);
        return;
    }

    // ---------------- generic slow path (warp-per-row, half 0 only) -----------
    if (half == 0 && row < B) {
        const unsigned KNEG = enc_f(-1e30f);
        __shared__ unsigned sG[2][32];
        sG[rib][lane] = KNEG;
        __syncwarp();

        unsigned locNon = KNEG, locWrong = KNEG, locPres = 0u;
        for (int i = lane; i < n; i += 32) {
            const unsigned long long pk = g_pack[i];
            const int c         = (int)(pk & 0xffffffffull);
            const unsigned bits = (unsigned)(pk >> 32);
            const long long o = (long long)row * C + c;
            const float xvv = __ldg(x + o);
            const unsigned key = enc_f(xvv);
            locNon = max(locNon, key);
            if (__ldg(yneg + o) != 0) locWrong = max(locWrong, key);
            if (__ldg(y    + o) != 0) locPres |= bits;
            unsigned bb = bits;
            while (bb) {
                const int l = __ffs(bb) - 1;
                bb &= bb - 1u;
                atomicMax(&sG[rib][l], key);
            }
        }
        #pragma unroll
        for (int off = 16; off > 0; off >>= 1) {
            locNon   = max(locNon,   __shfl_xor_sync(0xffffffffu, locNon,   off));
            locWrong = max(locWrong, __shfl_xor_sync(0xffffffffu, locWrong, off));
            locPres |= __shfl_xor_sync(0xffffffffu, locPres, off);
        }
        __syncwarp();
        if (lane == 0) {
            float loss;
            if (locPres) {
                const int fl = __ffs(locPres) - 1;
                loss = rank_loss_(sigmoidf_(dec_f(sG[rib][fl])), 0.5f);
            } else {
                loss = 0.5f * rank_loss_(0.5f, sigmoidf_(dec_f(locNon)))
                     + 0.5f * rank_loss_(0.5f, sigmoidf_(dec_f(locWrong)));
            }
            atomicAdd(out, loss);
        }
    }
}

// ---------------------------------------------------------------------------
extern "C" void kernel_launch(void* const* d_in, const int* in_sizes, int n_in,
                              void* d_out, int out_size) {
    const float* x    = (const float*)d_in[0];
    const int*   y    = (const int*)d_in[1];
    const int*   yneg = (const int*)d_in[2];
    const void*  wl   = d_in[3];

    const int C = 9605;
    const int L = in_sizes[3] / C;            // 20
    const int B = in_sizes[0] / C;            // 4096

    float* out = (float*)d_out;

    init_kernel<<<1, 256>>>(out, out_size, (const unsigned int*)wl, 256);
    build_bits_kernel<<<(C + 255) / 256, 256>>>(wl, C, L);
    compact_kernel<<<(C + 255) / 256, 256>>>(C);
    row_loss_kernel<<<(B + 1) / 2, 128>>>(x, y, yneg, C, B, out);
}